// round 2
// baseline (speedup 1.0000x reference)
#include <cuda_runtime.h>

#define NN 100000
#define D  128
#define MT 64   // node rows per GEMM block

// Scratch (allocation-free): two ping-pong activation buffers.
__device__ float g_h0[(size_t)NN * D];
__device__ float g_h1[(size_t)NN * D];

// ---------------------------------------------------------------------------
// Kernel 1: h0 = x   (GIN with eps=0: h = x + sum_neighbors)
// ---------------------------------------------------------------------------
__global__ void copy_x_kernel(const float4* __restrict__ x,
                              float4* __restrict__ h, int n4) {
    int i = blockIdx.x * blockDim.x + threadIdx.x;
    if (i < n4) h[i] = x[i];
}

// ---------------------------------------------------------------------------
// Kernel 2: warp-per-edge scatter-add. Each lane handles 4 floats via a
// vectorized red.global.add.v4.f32 (sm_90+), cutting atomic op count 4x.
// edge_index is int32 (JAX x64 disabled downcasts int64 -> int32).
// ---------------------------------------------------------------------------
__global__ void scatter_kernel(const int* __restrict__ ei,
                               const float* __restrict__ x,
                               float* __restrict__ h, int nE) {
    int gt = blockIdx.x * blockDim.x + threadIdx.x;
    int e = gt >> 5;
    if (e >= nE) return;
    int lane = gt & 31;
    int s = ei[e];
    int d = ei[nE + e];
    float4 v = ((const float4*)(x + (size_t)s * D))[lane];
    float* dp = h + (size_t)d * D + lane * 4;
    asm volatile("red.global.add.v4.f32 [%0], {%1,%2,%3,%4};"
                 :: "l"(dp), "f"(v.x), "f"(v.y), "f"(v.z), "f"(v.w)
                 : "memory");
}

// ---------------------------------------------------------------------------
// Kernel 3 (x3): out[r][n] = relu( sum_k hin[r][k]*W[k][n] + b[n] )
// Tile: 64 rows x 128 cols, K=128 fully staged. Block = 256 threads,
// each thread computes a 4x8 register tile -> 32 accumulators, FFMA-bound.
// ---------------------------------------------------------------------------
__global__ __launch_bounds__(256)
void gemm_relu_kernel(const float* __restrict__ hin,
                      const float* __restrict__ W,
                      const float* __restrict__ bias,
                      float* __restrict__ hout, int nrows) {
    extern __shared__ float smem[];
    float* Ws = smem;             // [128][128]
    float* Hs = smem + D * D;     // [MT][HP]
    const int HP = D + 4;

    int tid  = threadIdx.x;
    int row0 = blockIdx.x * MT;

    // Stage W: 16384 floats = 4096 float4, 16 per thread.
    #pragma unroll
    for (int t = 0; t < (D * D / 4) / 256; t++) {
        int idx = tid + t * 256;
        ((float4*)Ws)[idx] = ((const float4*)W)[idx];
    }

    // Stage H tile: 64 rows x 32 float4, 8 per thread (coalesced).
    #pragma unroll
    for (int t = 0; t < (MT * (D / 4)) / 256; t++) {
        int idx = tid + t * 256;
        int r   = idx >> 5;
        int c4  = idx & 31;
        int gr  = row0 + r;
        float4 v = make_float4(0.f, 0.f, 0.f, 0.f);
        if (gr < nrows) v = ((const float4*)(hin + (size_t)gr * D))[c4];
        *(float4*)(Hs + r * HP + c4 * 4) = v;
    }
    __syncthreads();

    int tx = tid & 15;   // cols tx*8 .. tx*8+7
    int ty = tid >> 4;   // rows ty*4 .. ty*4+3

    float acc[4][8];
    #pragma unroll
    for (int i = 0; i < 4; i++)
        #pragma unroll
        for (int j = 0; j < 8; j++) acc[i][j] = 0.f;

    const float* wrow = Ws + tx * 8;
    const float* hcol = Hs + (ty * 4) * HP;

    #pragma unroll 4
    for (int k = 0; k < D; k++) {
        float4 w0 = *(const float4*)(wrow + k * D);
        float4 w1 = *(const float4*)(wrow + k * D + 4);
        float wv[8] = {w0.x, w0.y, w0.z, w0.w, w1.x, w1.y, w1.z, w1.w};
        float hv[4];
        #pragma unroll
        for (int i = 0; i < 4; i++) hv[i] = hcol[i * HP + k];
        #pragma unroll
        for (int i = 0; i < 4; i++)
            #pragma unroll
            for (int j = 0; j < 8; j++)
                acc[i][j] = fmaf(hv[i], wv[j], acc[i][j]);
    }

    // Epilogue: bias + relu, vectorized stores.
    float bv[8];
    #pragma unroll
    for (int j = 0; j < 8; j++) bv[j] = __ldg(&bias[tx * 8 + j]);

    #pragma unroll
    for (int i = 0; i < 4; i++) {
        int gr = row0 + ty * 4 + i;
        if (gr < nrows) {
            float4 o0, o1;
            o0.x = fmaxf(acc[i][0] + bv[0], 0.f);
            o0.y = fmaxf(acc[i][1] + bv[1], 0.f);
            o0.z = fmaxf(acc[i][2] + bv[2], 0.f);
            o0.w = fmaxf(acc[i][3] + bv[3], 0.f);
            o1.x = fmaxf(acc[i][4] + bv[4], 0.f);
            o1.y = fmaxf(acc[i][5] + bv[5], 0.f);
            o1.z = fmaxf(acc[i][6] + bv[6], 0.f);
            o1.w = fmaxf(acc[i][7] + bv[7], 0.f);
            float* op = hout + (size_t)gr * D + tx * 8;
            *(float4*)(op)     = o0;
            *(float4*)(op + 4) = o1;
        }
    }
}

// ---------------------------------------------------------------------------
extern "C" void kernel_launch(void* const* d_in, const int* in_sizes, int n_in,
                              void* d_out, int out_size) {
    const float* x  = (const float*)d_in[0];
    const float* W1 = (const float*)d_in[1];
    const float* b1 = (const float*)d_in[2];
    const float* W2 = (const float*)d_in[3];
    const float* b2 = (const float*)d_in[4];
    const float* W3 = (const float*)d_in[5];
    const float* b3 = (const float*)d_in[6];
    const int*   ei = (const int*)d_in[7];   // int32: JAX x64 disabled
    float* out = (float*)d_out;

    int nE = in_sizes[7] / 2;   // 3,200,000

    float *h0, *h1;
    cudaGetSymbolAddress((void**)&h0, g_h0);
    cudaGetSymbolAddress((void**)&h1, g_h1);

    // h0 = x
    int n4 = (NN * D) / 4;
    copy_x_kernel<<<(n4 + 255) / 256, 256>>>((const float4*)x, (float4*)h0, n4);

    // h0 += segment_sum(x[src] -> dst)
    long long threads = (long long)nE * 32;
    int sblocks = (int)((threads + 255) / 256);
    scatter_kernel<<<sblocks, 256>>>(ei, x, h0, nE);

    // 3-layer MLP with ReLU
    int smem_bytes = (D * D + MT * (D + 4)) * (int)sizeof(float);
    cudaFuncSetAttribute(gemm_relu_kernel,
                         cudaFuncAttributeMaxDynamicSharedMemorySize, smem_bytes);
    int gblocks = (NN + MT - 1) / MT;
    gemm_relu_kernel<<<gblocks, 256, smem_bytes>>>(h0, W1, b1, h1, NN);
    gemm_relu_kernel<<<gblocks, 256, smem_bytes>>>(h1, W2, b2, h0, NN);
    gemm_relu_kernel<<<gblocks, 256, smem_bytes>>>(h0, W3, b3, out, NN);
}

// round 3
// speedup vs baseline: 1.6735x; 1.6735x over previous
#include <cuda_runtime.h>

#define NN   100000
#define D    128
#define MAXE 3400000

// ---------------------------------------------------------------------------
// Allocation-free scratch
// ---------------------------------------------------------------------------
__device__ float g_h0[(size_t)NN * D];
__device__ float g_h1[(size_t)NN * D];
__device__ int   g_cnt[NN];     // per-node in-degree
__device__ int   g_inc[NN];     // inclusive scan (per chunk)
__device__ int   g_rs[NN];      // CSR row start
__device__ int   g_cur[NN];     // fill cursor
__device__ int   g_srcs[MAXE];  // CSR-sorted source node ids
__device__ int   g_bsums[128];  // scan block sums

static __device__ __forceinline__ float4 add4(float4 a, float4 b) {
    return make_float4(a.x + b.x, a.y + b.y, a.z + b.z, a.w + b.w);
}

// ---------------------------------------------------------------------------
// CSR build: histogram -> scan -> fill
// ---------------------------------------------------------------------------
__global__ void zero_cnt_kernel() {
    int i = blockIdx.x * blockDim.x + threadIdx.x;
    if (i < NN) g_cnt[i] = 0;
}

__global__ void hist_kernel(const int* __restrict__ ei, int nE) {
    int e = blockIdx.x * blockDim.x + threadIdx.x;
    if (e < nE) atomicAdd(&g_cnt[ei[nE + e]], 1);
}

__global__ void scan1_kernel() {   // inclusive scan of 1024-chunks
    __shared__ int sm[1024];
    int t = threadIdx.x, b = blockIdx.x;
    int i = b * 1024 + t;
    sm[t] = (i < NN) ? g_cnt[i] : 0;
    __syncthreads();
    #pragma unroll
    for (int off = 1; off < 1024; off <<= 1) {
        int add = (t >= off) ? sm[t - off] : 0;
        __syncthreads();
        sm[t] += add;
        __syncthreads();
    }
    if (i < NN) g_inc[i] = sm[t];
    if (t == 1023) g_bsums[b] = sm[t];
}

__global__ void scan2_kernel(int nb) {  // serial exclusive scan of ~98 sums
    if (threadIdx.x == 0 && blockIdx.x == 0) {
        int ex = 0;
        for (int b = 0; b < nb; b++) { int v = g_bsums[b]; g_bsums[b] = ex; ex += v; }
    }
}

__global__ void scan3_kernel() {
    int i = blockIdx.x * blockDim.x + threadIdx.x;
    if (i < NN) {
        int rs = g_inc[i] - g_cnt[i] + g_bsums[i >> 10];
        g_rs[i] = rs;
        g_cur[i] = rs;
    }
}

__global__ void fill_kernel(const int* __restrict__ ei, int nE) {
    int e = blockIdx.x * blockDim.x + threadIdx.x;
    if (e < nE) {
        int s = ei[e], d = ei[nE + e];
        int pos = atomicAdd(&g_cur[d], 1);
        g_srcs[pos] = s;
    }
}

// ---------------------------------------------------------------------------
// Gather: warp per node. h0[n] = x[n] + sum_{s in neighbors(n)} x[s].
// Lane owns 4 floats (float4). 4-way unroll for MLP.
// ---------------------------------------------------------------------------
__global__ __launch_bounds__(256)
void gather_kernel(const float* __restrict__ x, float* __restrict__ h) {
    int n = blockIdx.x * 8 + (threadIdx.x >> 5);
    if (n >= NN) return;
    int lane = threadIdx.x & 31;
    const float4* xv = (const float4*)x;

    float4 a0 = xv[(size_t)n * 32 + lane];
    float4 a1 = make_float4(0.f, 0.f, 0.f, 0.f);
    float4 a2 = a1, a3 = a1;

    int start = g_rs[n], c = g_cnt[n];
    const int* sp = g_srcs + start;
    int j = 0;
    for (; j + 4 <= c; j += 4) {
        int s0 = sp[j], s1 = sp[j + 1], s2 = sp[j + 2], s3 = sp[j + 3];
        float4 v0 = xv[(size_t)s0 * 32 + lane];
        float4 v1 = xv[(size_t)s1 * 32 + lane];
        float4 v2 = xv[(size_t)s2 * 32 + lane];
        float4 v3 = xv[(size_t)s3 * 32 + lane];
        a0 = add4(a0, v0); a1 = add4(a1, v1);
        a2 = add4(a2, v2); a3 = add4(a3, v3);
    }
    for (; j < c; j++) {
        int s = sp[j];
        a0 = add4(a0, xv[(size_t)s * 32 + lane]);
    }
    ((float4*)h)[(size_t)n * 32 + lane] = add4(add4(a0, a1), add4(a2, a3));
}

// ---------------------------------------------------------------------------
// GEMM + bias + ReLU: out[r][n] = relu(sum_k h[r][k]*W[k][n] + b[n])
// Tile 64 rows x 128 cols, K=128 staged. 128 threads, 8x8 regs/thread.
// Smem: W[128][128] (64KB) + H[64][132] (33.8KB) = 97KB -> 2 blocks/SM.
// ---------------------------------------------------------------------------
#define MT 64
#define HP (D + 4)

__global__ __launch_bounds__(128)
void gemm_relu_kernel(const float* __restrict__ hin,
                      const float* __restrict__ W,
                      const float* __restrict__ bias,
                      float* __restrict__ hout, int nrows) {
    extern __shared__ float smem[];
    float* Ws = smem;           // [128][128]
    float* Hs = smem + D * D;   // [MT][HP]

    int tid  = threadIdx.x;
    int row0 = blockIdx.x * MT;

    // Stage W: 4096 float4, 32 per thread.
    #pragma unroll
    for (int t = 0; t < (D * D / 4) / 128; t++) {
        int idx = tid + t * 128;
        ((float4*)Ws)[idx] = ((const float4*)W)[idx];
    }
    // Stage H: 64 rows x 32 float4 = 2048, 16 per thread (coalesced).
    #pragma unroll
    for (int t = 0; t < (MT * (D / 4)) / 128; t++) {
        int idx = tid + t * 128;
        int r   = idx >> 5;
        int c4  = idx & 31;
        int gr  = row0 + r;
        float4 v = make_float4(0.f, 0.f, 0.f, 0.f);
        if (gr < nrows) v = ((const float4*)(hin + (size_t)gr * D))[c4];
        *(float4*)(Hs + r * HP + c4 * 4) = v;
    }
    __syncthreads();

    int tx = tid & 15;   // cols tx*8..+7
    int ty = tid >> 4;   // rows ty*8..+7 (ty 0..7)

    float acc[8][8];
    #pragma unroll
    for (int i = 0; i < 8; i++)
        #pragma unroll
        for (int j = 0; j < 8; j++) acc[i][j] = 0.f;

    const float* wp = Ws + tx * 8;
    const float* hp = Hs + (ty * 8) * HP;

    #pragma unroll 4
    for (int k = 0; k < D; k++) {
        float4 w0 = *(const float4*)(wp + k * D);
        float4 w1 = *(const float4*)(wp + k * D + 4);
        float wv[8] = {w0.x, w0.y, w0.z, w0.w, w1.x, w1.y, w1.z, w1.w};
        float hv[8];
        #pragma unroll
        for (int i = 0; i < 8; i++) hv[i] = hp[i * HP + k];
        #pragma unroll
        for (int i = 0; i < 8; i++)
            #pragma unroll
            for (int j = 0; j < 8; j++)
                acc[i][j] = fmaf(hv[i], wv[j], acc[i][j]);
    }

    float bv[8];
    #pragma unroll
    for (int j = 0; j < 8; j++) bv[j] = __ldg(&bias[tx * 8 + j]);

    #pragma unroll
    for (int i = 0; i < 8; i++) {
        int gr = row0 + ty * 8 + i;
        if (gr < nrows) {
            float4 o0, o1;
            o0.x = fmaxf(acc[i][0] + bv[0], 0.f);
            o0.y = fmaxf(acc[i][1] + bv[1], 0.f);
            o0.z = fmaxf(acc[i][2] + bv[2], 0.f);
            o0.w = fmaxf(acc[i][3] + bv[3], 0.f);
            o1.x = fmaxf(acc[i][4] + bv[4], 0.f);
            o1.y = fmaxf(acc[i][5] + bv[5], 0.f);
            o1.z = fmaxf(acc[i][6] + bv[6], 0.f);
            o1.w = fmaxf(acc[i][7] + bv[7], 0.f);
            float* op = hout + (size_t)gr * D + tx * 8;
            *(float4*)(op)     = o0;
            *(float4*)(op + 4) = o1;
        }
    }
}

// ---------------------------------------------------------------------------
extern "C" void kernel_launch(void* const* d_in, const int* in_sizes, int n_in,
                              void* d_out, int out_size) {
    const float* x  = (const float*)d_in[0];
    const float* W1 = (const float*)d_in[1];
    const float* b1 = (const float*)d_in[2];
    const float* W2 = (const float*)d_in[3];
    const float* b2 = (const float*)d_in[4];
    const float* W3 = (const float*)d_in[5];
    const float* b3 = (const float*)d_in[6];
    const int*   ei = (const int*)d_in[7];   // int32 (JAX x64 disabled)
    float* out = (float*)d_out;

    int nE = in_sizes[7] / 2;
    if (nE > MAXE) nE = MAXE;

    float *h0, *h1;
    cudaGetSymbolAddress((void**)&h0, g_h0);
    cudaGetSymbolAddress((void**)&h1, g_h1);

    // --- CSR build ---
    zero_cnt_kernel<<<(NN + 255) / 256, 256>>>();
    hist_kernel<<<(nE + 255) / 256, 256>>>(ei, nE);
    int nb = (NN + 1023) / 1024;
    scan1_kernel<<<nb, 1024>>>();
    scan2_kernel<<<1, 32>>>(nb);
    scan3_kernel<<<(NN + 255) / 256, 256>>>();
    fill_kernel<<<(nE + 255) / 256, 256>>>(ei, nE);

    // --- gather: h0 = x + segment_sum(x[src] -> dst) ---
    gather_kernel<<<(NN + 7) / 8, 256>>>(x, h0);

    // --- 3-layer MLP with ReLU ---
    int smem_bytes = (D * D + MT * HP) * (int)sizeof(float);
    cudaFuncSetAttribute(gemm_relu_kernel,
                         cudaFuncAttributeMaxDynamicSharedMemorySize, smem_bytes);
    int gblocks = (NN + MT - 1) / MT;
    gemm_relu_kernel<<<gblocks, 128, smem_bytes>>>(h0, W1, b1, h1, NN);
    gemm_relu_kernel<<<gblocks, 128, smem_bytes>>>(h1, W2, b2, h0, NN);
    gemm_relu_kernel<<<gblocks, 128, smem_bytes>>>(h0, W3, b3, out, NN);
}

// round 5
// speedup vs baseline: 2.2643x; 1.3531x over previous
#include <cuda_runtime.h>
#include <cuda_bf16.h>
#include <cstdint>

#define NN   100000
#define D    128
#define MAXE 3400000
#define NT   ((NN + 127) / 128)
#define TILE_U4 2048   // uint4 per 32KB bf16 128x128 image

// ---------------------------------------------------------------------------
// Allocation-free scratch
// ---------------------------------------------------------------------------
__device__ float g_h0[(size_t)NN * D];
__device__ float g_h1[(size_t)NN * D];
__device__ int   g_cnt[NN];
__device__ int   g_inc[NN];
__device__ int   g_rs[NN];
__device__ int   g_cur[NN];
__device__ int   g_srcs[MAXE];
__device__ int   g_bsums[128];
// W bf16 hi/lo images, XOR-swizzled [k][n] layout, 32KB each
__device__ uint4 g_w_hi[3 * TILE_U4];
__device__ uint4 g_w_lo[3 * TILE_U4];

static __device__ __forceinline__ float4 add4(float4 a, float4 b) {
    return make_float4(a.x + b.x, a.y + b.y, a.z + b.z, a.w + b.w);
}

static __device__ __forceinline__ uint32_t s2u(const void* p) {
    uint32_t a;
    asm("{ .reg .u64 t; cvta.to.shared.u64 t, %1; cvt.u32.u64 %0, t; }"
        : "=r"(a) : "l"(p));
    return a;
}

static __device__ __forceinline__ uint32_t pack_bf2(float a, float b) {
    __nv_bfloat162 t = __floats2bfloat162_rn(a, b);
    return *(uint32_t*)&t;
}

// mma.sync m16n8k16 row.col f32.bf16.bf16.f32
static __device__ __forceinline__ void mma16816(float* c, const uint32_t* a,
                                                uint32_t b0, uint32_t b1) {
    asm volatile(
        "mma.sync.aligned.m16n8k16.row.col.f32.bf16.bf16.f32 "
        "{%0,%1,%2,%3}, {%4,%5,%6,%7}, {%8,%9}, {%0,%1,%2,%3};"
        : "+f"(c[0]), "+f"(c[1]), "+f"(c[2]), "+f"(c[3])
        : "r"(a[0]), "r"(a[1]), "r"(a[2]), "r"(a[3]), "r"(b0), "r"(b1));
}

static __device__ __forceinline__ void ldsm_x4(uint32_t* r, uint32_t addr) {
    asm volatile("ldmatrix.sync.aligned.m8n8.x4.shared.b16 {%0,%1,%2,%3}, [%4];"
                 : "=r"(r[0]), "=r"(r[1]), "=r"(r[2]), "=r"(r[3]) : "r"(addr));
}
static __device__ __forceinline__ void ldsm_x4t(uint32_t* r, uint32_t addr) {
    asm volatile("ldmatrix.sync.aligned.m8n8.x4.trans.shared.b16 {%0,%1,%2,%3}, [%4];"
                 : "=r"(r[0]), "=r"(r[1]), "=r"(r[2]), "=r"(r[3]) : "r"(addr));
}

// tile byte offset: row-major 128x128 bf16, 256B/row, 16B column groups
// XOR-swizzled so ldmatrix (8 rows, fixed logical group) is conflict-free.
static __device__ __forceinline__ uint32_t toff(int row, int g) {
    return (uint32_t)row * 256u + (uint32_t)((g ^ (row & 7)) << 4);
}

// ---------------------------------------------------------------------------
// CSR build
// ---------------------------------------------------------------------------
__global__ void zero_cnt_kernel() {
    int i = blockIdx.x * blockDim.x + threadIdx.x;
    if (i < NN) g_cnt[i] = 0;
}

__global__ void hist_kernel(const int* __restrict__ ei, int nE) {
    int e = blockIdx.x * blockDim.x + threadIdx.x;
    if (e < nE) atomicAdd(&g_cnt[ei[nE + e]], 1);
}

__global__ void scan1_kernel() {
    __shared__ int sm[1024];
    int t = threadIdx.x, b = blockIdx.x;
    int i = b * 1024 + t;
    sm[t] = (i < NN) ? g_cnt[i] : 0;
    __syncthreads();
    #pragma unroll
    for (int off = 1; off < 1024; off <<= 1) {
        int add = (t >= off) ? sm[t - off] : 0;
        __syncthreads();
        sm[t] += add;
        __syncthreads();
    }
    if (i < NN) g_inc[i] = sm[t];
    if (t == 1023) g_bsums[b] = sm[t];
}

__global__ void scan2_kernel(int nb) {
    __shared__ int sm[128];
    int t = threadIdx.x;
    int v = (t < nb) ? g_bsums[t] : 0;
    sm[t] = v;
    __syncthreads();
    #pragma unroll
    for (int off = 1; off < 128; off <<= 1) {
        int add = (t >= off) ? sm[t - off] : 0;
        __syncthreads();
        sm[t] += add;
        __syncthreads();
    }
    if (t < nb) g_bsums[t] = sm[t] - v;
}

__global__ void scan3_kernel() {
    int i = blockIdx.x * blockDim.x + threadIdx.x;
    if (i < NN) {
        int rs = g_inc[i] - g_cnt[i] + g_bsums[i >> 10];
        g_rs[i] = rs;
        g_cur[i] = rs;
    }
}

__global__ void fill_kernel(const int* __restrict__ ei, int nE) {
    int e = blockIdx.x * blockDim.x + threadIdx.x;
    if (e < nE) {
        int s = ei[e], d = ei[nE + e];
        int pos = atomicAdd(&g_cur[d], 1);
        g_srcs[pos] = s;
    }
}

// ---------------------------------------------------------------------------
// Prep W: fp32 [k][n] -> bf16 hi/lo swizzled images. grid=3.
// ---------------------------------------------------------------------------
__global__ void prep_w_kernel(const float* __restrict__ W1,
                              const float* __restrict__ W2,
                              const float* __restrict__ W3) {
    const float* W = (blockIdx.x == 0) ? W1 : (blockIdx.x == 1) ? W2 : W3;
    char* hi = (char*)g_w_hi + (size_t)blockIdx.x * 32768;
    char* lo = (char*)g_w_lo + (size_t)blockIdx.x * 32768;
    for (int i = threadIdx.x; i < D * D / 4; i += blockDim.x) {
        int k = i >> 5, c4 = i & 31;
        float4 v = ((const float4*)W)[i];
        float hx = __bfloat162float(__float2bfloat16(v.x));
        float hy = __bfloat162float(__float2bfloat16(v.y));
        float hz = __bfloat162float(__float2bfloat16(v.z));
        float hw = __bfloat162float(__float2bfloat16(v.w));
        uint2 hv = make_uint2(pack_bf2(v.x, v.y), pack_bf2(v.z, v.w));
        uint2 lv = make_uint2(pack_bf2(v.x - hx, v.y - hy), pack_bf2(v.z - hz, v.w - hw));
        uint32_t off = toff(k, c4 >> 1) + (c4 & 1) * 8;
        *(uint2*)(hi + off) = hv;
        *(uint2*)(lo + off) = lv;
    }
}

// ---------------------------------------------------------------------------
// Gather: warp per node. h0[n] = x[n] + sum_{neighbors} x[s]  (fp32).
// ---------------------------------------------------------------------------
__global__ __launch_bounds__(256)
void gather_kernel(const float* __restrict__ x, float* __restrict__ h) {
    int n = blockIdx.x * 8 + (threadIdx.x >> 5);
    if (n >= NN) return;
    int lane = threadIdx.x & 31;
    const float4* xv = (const float4*)x;

    float4 a0 = xv[(size_t)n * 32 + lane];
    float4 a1 = make_float4(0.f, 0.f, 0.f, 0.f);
    float4 a2 = a1, a3 = a1;

    int start = g_rs[n], c = g_cnt[n];
    const int* sp = g_srcs + start;
    int j = 0;
    for (; j + 4 <= c; j += 4) {
        int s0 = sp[j], s1 = sp[j + 1], s2 = sp[j + 2], s3 = sp[j + 3];
        a0 = add4(a0, xv[(size_t)s0 * 32 + lane]);
        a1 = add4(a1, xv[(size_t)s1 * 32 + lane]);
        a2 = add4(a2, xv[(size_t)s2 * 32 + lane]);
        a3 = add4(a3, xv[(size_t)s3 * 32 + lane]);
    }
    for (; j < c; j++)
        a0 = add4(a0, xv[(size_t)sp[j] * 32 + lane]);
    ((float4*)h)[(size_t)n * 32 + lane] = add4(add4(a0, a1), add4(a2, a3));
}

// ---------------------------------------------------------------------------
// HMMA split-bf16 layer: out = relu(A @ W + b), tile 128x128, K=128.
// Smem: Whi(32K) Wlo(32K) Ahi(32K) Alo(32K) bias(512B).
// ---------------------------------------------------------------------------
#define WH_OFF 0
#define WL_OFF 32768
#define AH_OFF 65536
#define AL_OFF 98304
#define BIAS_OFF 131072
#define SM_TOTAL (131072 + 512)

__global__ __launch_bounds__(256, 1)
void mma_layer_kernel(const float* __restrict__ hin,
                      const uint4* __restrict__ Whi, const uint4* __restrict__ Wlo,
                      const float* __restrict__ bias,
                      float* __restrict__ hout, int nrows) {
    extern __shared__ char smem[];
    uint32_t sb = s2u(smem);
    int tid = threadIdx.x;
    int row0 = blockIdx.x * 128;

    // Stage W hi/lo (verbatim, swizzle preserved)
    #pragma unroll
    for (int t = 0; t < 8; t++) {
        int i = tid + t * 256;
        ((uint4*)(smem + WH_OFF))[i] = Whi[i];
        ((uint4*)(smem + WL_OFF))[i] = Wlo[i];
    }
    // Stage A: fp32 -> bf16 hi/lo, swizzled
    #pragma unroll
    for (int t = 0; t < 16; t++) {
        int i = tid + t * 256;
        int row = i >> 5, c4 = i & 31;
        int grow = row0 + row;
        float4 v = make_float4(0.f, 0.f, 0.f, 0.f);
        if (grow < nrows) v = ((const float4*)(hin + (size_t)grow * D))[c4];
        float hx = __bfloat162float(__float2bfloat16(v.x));
        float hy = __bfloat162float(__float2bfloat16(v.y));
        float hz = __bfloat162float(__float2bfloat16(v.z));
        float hw = __bfloat162float(__float2bfloat16(v.w));
        uint2 hv = make_uint2(pack_bf2(v.x, v.y), pack_bf2(v.z, v.w));
        uint2 lv = make_uint2(pack_bf2(v.x - hx, v.y - hy), pack_bf2(v.z - hz, v.w - hw));
        uint32_t off = toff(row, c4 >> 1) + (c4 & 1) * 8;
        *(uint2*)(smem + AH_OFF + off) = hv;
        *(uint2*)(smem + AL_OFF + off) = lv;
    }
    if (tid < 32) ((float4*)(smem + BIAS_OFF))[tid] = ((const float4*)bias)[tid];
    __syncthreads();

    int wid = tid >> 5, lane = tid & 31;
    int mrow = wid * 16;

    float acc[16][4];
    #pragma unroll
    for (int i = 0; i < 16; i++)
        #pragma unroll
        for (int j = 0; j < 4; j++) acc[i][j] = 0.f;

    int arow = mrow + (lane & 15);
    int asel = lane >> 4;
    int axor = arow & 7;
    uint32_t a_base = sb + AH_OFF + (uint32_t)arow * 256u;

    int brow = lane & 15;
    int bsel = lane >> 4;

    #pragma unroll
    for (int ks = 0; ks < 8; ks++) {
        uint32_t ag = (uint32_t)(((ks * 2 + asel) ^ axor) << 4);
        uint32_t ahi[4], alo[4];
        ldsm_x4(ahi, a_base + ag);
        ldsm_x4(alo, a_base + 32768u + ag);   // AL = AH + 32K

        int brr = ks * 16 + brow;
        uint32_t b_base = sb + WH_OFF + (uint32_t)brr * 256u;
        int bxor = brr & 7;

        #pragma unroll
        for (int p = 0; p < 8; p++) {
            uint32_t bg = (uint32_t)(((p * 2 + bsel) ^ bxor) << 4);
            uint32_t bh[4], bl[4];
            ldsm_x4t(bh, b_base + bg);
            ldsm_x4t(bl, b_base + 32768u + bg);  // WL = WH + 32K
            mma16816(acc[2 * p],     ahi, bh[0], bh[1]);
            mma16816(acc[2 * p + 1], ahi, bh[2], bh[3]);
            mma16816(acc[2 * p],     ahi, bl[0], bl[1]);
            mma16816(acc[2 * p + 1], ahi, bl[2], bl[3]);
            mma16816(acc[2 * p],     alo, bh[0], bh[1]);
            mma16816(acc[2 * p + 1], alo, bh[2], bh[3]);
        }
    }

    // Epilogue: bias + relu. c0,c1 -> row lane/4; c2,c3 -> row lane/4+8.
    const float* bs = (const float*)(smem + BIAS_OFF);
    int rbase = mrow + (lane >> 2);
    int col0 = (lane & 3) * 2;
    #pragma unroll
    for (int half = 0; half < 2; half++) {
        int grow = row0 + rbase + half * 8;
        if (grow < nrows) {
            float* op = hout + (size_t)grow * D;
            #pragma unroll
            for (int nt = 0; nt < 16; nt++) {
                int c = nt * 8 + col0;
                float2 o;
                o.x = fmaxf(acc[nt][half * 2 + 0] + bs[c], 0.f);
                o.y = fmaxf(acc[nt][half * 2 + 1] + bs[c + 1], 0.f);
                *(float2*)(op + c) = o;
            }
        }
    }
}

// ---------------------------------------------------------------------------
extern "C" void kernel_launch(void* const* d_in, const int* in_sizes, int n_in,
                              void* d_out, int out_size) {
    const float* x  = (const float*)d_in[0];
    const float* W1 = (const float*)d_in[1];
    const float* b1 = (const float*)d_in[2];
    const float* W2 = (const float*)d_in[3];
    const float* b2 = (const float*)d_in[4];
    const float* W3 = (const float*)d_in[5];
    const float* b3 = (const float*)d_in[6];
    const int*   ei = (const int*)d_in[7];   // int32 (JAX x64 disabled)
    float* out = (float*)d_out;

    int nE = in_sizes[7] / 2;
    if (nE > MAXE) nE = MAXE;

    float *h0, *h1;
    uint4 *wHi, *wLo;
    cudaGetSymbolAddress((void**)&h0, g_h0);
    cudaGetSymbolAddress((void**)&h1, g_h1);
    cudaGetSymbolAddress((void**)&wHi, g_w_hi);
    cudaGetSymbolAddress((void**)&wLo, g_w_lo);

    // --- CSR build + weight prep ---
    zero_cnt_kernel<<<(NN + 255) / 256, 256>>>();
    prep_w_kernel<<<3, 256>>>(W1, W2, W3);
    hist_kernel<<<(nE + 255) / 256, 256>>>(ei, nE);
    int nb = (NN + 1023) / 1024;
    scan1_kernel<<<nb, 1024>>>();
    scan2_kernel<<<1, 128>>>(nb);
    scan3_kernel<<<(NN + 255) / 256, 256>>>();
    fill_kernel<<<(nE + 255) / 256, 256>>>(ei, nE);

    // --- gather ---
    gather_kernel<<<(NN + 7) / 8, 256>>>(x, h0);

    // --- 3 HMMA layers ---
    cudaFuncSetAttribute(mma_layer_kernel,
                         cudaFuncAttributeMaxDynamicSharedMemorySize, SM_TOTAL);
    mma_layer_kernel<<<NT, 256, SM_TOTAL>>>(h0, wHi,               wLo,               b1, h1, NN);
    mma_layer_kernel<<<NT, 256, SM_TOTAL>>>(h1, wHi + TILE_U4,     wLo + TILE_U4,     b2, h0, NN);
    mma_layer_kernel<<<NT, 256, SM_TOTAL>>>(h0, wHi + 2 * TILE_U4, wLo + 2 * TILE_U4, b3, out, NN);
}